// round 3
// baseline (speedup 1.0000x reference)
#include <cuda_runtime.h>
#include <cstddef>

// Problem constants (fixed by the reference)
#define NN  50000          // nodes
#define NE  800000         // edges
#define SSN 2              // samples
#define DIN 128            // input dim
#define DNZ 64             // noise dim
#define DH0 192            // DIN + DNZ
#define DO  256            // hidden / output dim
#define MTOT (SSN * NN)    // 100000 GEMM rows

// ---------------------------------------------------------------------------
// Static device scratch (no allocation allowed in kernel_launch)
// ---------------------------------------------------------------------------
__device__ int   g_row_start[NN + 1];
__device__ int   g_cursor[NN];
__device__ int   g_csr_src[NE];
__device__ float g_z0[(size_t)SSN * NN * DH0];   // 76.8 MB
__device__ float g_h1[(size_t)SSN * NN * DO];    // 102.4 MB
__device__ float g_z1[(size_t)SSN * NN * DO];    // 102.4 MB

// ---------------------------------------------------------------------------
// CSR build: count -> scan -> fill
// ---------------------------------------------------------------------------
__global__ void k_zero_cursor() {
    int i = blockIdx.x * blockDim.x + threadIdx.x;
    if (i < NN) g_cursor[i] = 0;
}

__global__ void k_count(const int* __restrict__ dst) {
    int e = blockIdx.x * blockDim.x + threadIdx.x;
    if (e < NE) atomicAdd(&g_cursor[dst[e]], 1);
}

// Single-block exclusive scan over g_cursor -> g_row_start (and reset cursor)
__global__ void k_scan() {
    __shared__ int warp_sums[32];
    __shared__ int s_carry;
    if (threadIdx.x == 0) s_carry = 0;
    __syncthreads();
    int lane = threadIdx.x & 31;
    int wid  = threadIdx.x >> 5;

    for (int base = 0; base < NN; base += 1024) {
        int i = base + (int)threadIdx.x;
        int v = (i < NN) ? g_cursor[i] : 0;
        // inclusive warp scan
        int x = v;
        #pragma unroll
        for (int o = 1; o < 32; o <<= 1) {
            int y = __shfl_up_sync(0xFFFFFFFFu, x, o);
            if (lane >= o) x += y;
        }
        if (lane == 31) warp_sums[wid] = x;
        __syncthreads();
        if (wid == 0) {
            int w = warp_sums[lane];
            #pragma unroll
            for (int o = 1; o < 32; o <<= 1) {
                int y = __shfl_up_sync(0xFFFFFFFFu, w, o);
                if (lane >= o) w += y;
            }
            warp_sums[lane] = w;
        }
        __syncthreads();
        int incl = x + (wid > 0 ? warp_sums[wid - 1] : 0) + s_carry;
        int excl = incl - v;
        if (i < NN) {
            g_row_start[i] = excl;
            g_cursor[i]    = excl;   // cursor doubles as insertion pointer
        }
        __syncthreads();
        if (threadIdx.x == 1023) s_carry = incl;  // running total
        __syncthreads();
    }
    if (threadIdx.x == 0) g_row_start[NN] = s_carry;
}

__global__ void k_fill(const int* __restrict__ src, const int* __restrict__ dst) {
    int e = blockIdx.x * blockDim.x + threadIdx.x;
    if (e < NE) {
        int d   = dst[e];
        int pos = atomicAdd(&g_cursor[d], 1);
        g_csr_src[pos] = src[e];
    }
}

// ---------------------------------------------------------------------------
// Layer-0 aggregation: z0[s,d,:] = (1+eps0)*h0[s,d,:] + sum_{(src)->d} h0[s,src,:]
// h0 = [X | eps], X shared across samples -> aggregate X part once.
// One block (256 threads) per node:
//   t in [0,128)   : X feature t      (shared across both samples)
//   t in [128,192) : eps s=0 feature (t-128)
//   t in [192,256) : eps s=1 feature (t-192)
// ---------------------------------------------------------------------------
__global__ __launch_bounds__(256) void k_agg0(const float* __restrict__ X,
                                              const float* __restrict__ eps,
                                              const float* __restrict__ eps0p) {
    int d = blockIdx.x;
    int t = threadIdx.x;
    __shared__ int s_nbr[128];
    int rs = g_row_start[d];
    int re = g_row_start[d + 1];

    const float* eps1s = eps + (size_t)NN * DNZ;

    float acc = 0.f;
    for (int c = rs; c < re; c += 128) {
        int n = min(128, re - c);
        __syncthreads();
        if (t < n) s_nbr[t] = g_csr_src[c + t];
        __syncthreads();
        #pragma unroll 4
        for (int k = 0; k < n; k++) {
            int s = s_nbr[k];
            if (t < 128)       acc += X[(size_t)s * DIN + t];
            else if (t < 192)  acc += eps[(size_t)s * DNZ + (t - 128)];
            else               acc += eps1s[(size_t)s * DNZ + (t - 192)];
        }
    }

    float e0 = 1.f + *eps0p;
    if (t < 128) {
        float v = e0 * X[(size_t)d * DIN + t] + acc;
        g_z0[(size_t)d * DH0 + t] = v;                              // s=0
        g_z0[(size_t)NN * DH0 + (size_t)d * DH0 + t] = v;           // s=1 (same X part)
    } else if (t < 192) {
        float v = e0 * eps[(size_t)d * DNZ + (t - 128)] + acc;
        g_z0[(size_t)d * DH0 + t] = v;
    } else {
        float v = e0 * eps1s[(size_t)d * DNZ + (t - 192)] + acc;
        g_z0[(size_t)NN * DH0 + (size_t)d * DH0 + 128 + (t - 192)] = v;
    }
}

// ---------------------------------------------------------------------------
// Layer-1 aggregation over h1 (256 features, both samples per thread)
// ---------------------------------------------------------------------------
__global__ __launch_bounds__(256) void k_agg1(const float* __restrict__ eps1p) {
    int d = blockIdx.x;
    int t = threadIdx.x;
    __shared__ int s_nbr[128];
    int rs = g_row_start[d];
    int re = g_row_start[d + 1];

    const float* h0s = g_h1;
    const float* h1s = g_h1 + (size_t)NN * DO;

    float a0 = 0.f, a1 = 0.f;
    for (int c = rs; c < re; c += 128) {
        int n = min(128, re - c);
        __syncthreads();
        if (t < n) s_nbr[t] = g_csr_src[c + t];
        __syncthreads();
        #pragma unroll 4
        for (int k = 0; k < n; k++) {
            int s = s_nbr[k];
            a0 += h0s[(size_t)s * DO + t];
            a1 += h1s[(size_t)s * DO + t];
        }
    }

    float e1 = 1.f + *eps1p;
    g_z1[(size_t)d * DO + t]                     = e1 * h0s[(size_t)d * DO + t] + a0;
    g_z1[(size_t)NN * DO + (size_t)d * DO + t]   = e1 * h1s[(size_t)d * DO + t] + a1;
}

// ---------------------------------------------------------------------------
// SGEMM: C[M, 256] = relu(A[M, K] @ W[K, 256] + b), M = 100000
// 128x128 tile, BK=16, 256 threads, 8x8 micro-tile.
// ---------------------------------------------------------------------------
template <int K>
__global__ __launch_bounds__(256) void k_gemm(const float* __restrict__ A,
                                              const float* __restrict__ W,
                                              const float* __restrict__ bias,
                                              float* __restrict__ C) {
    const int M = MTOT;
    __shared__ float As[16][132];  // transposed A tile, pad 4 keeps f4 align + no bank conflict
    __shared__ float Ws[16][128];

    int tid = threadIdx.x;
    int m0  = blockIdx.x * 128;
    int n0  = blockIdx.y * 128;
    int tm  = (tid >> 4) << 3;   // 0..120 step 8
    int tn  = (tid & 15) << 3;

    float acc[8][8];
    #pragma unroll
    for (int i = 0; i < 8; i++)
        #pragma unroll
        for (int j = 0; j < 8; j++) acc[i][j] = 0.f;

    for (int k0 = 0; k0 < K; k0 += 16) {
        // Load A tile (128 rows x 16 k) transposed into As
        #pragma unroll
        for (int i = 0; i < 2; i++) {
            int idx = tid + i * 256;       // 0..511
            int row = idx >> 2;            // 0..127
            int kq  = (idx & 3) << 2;      // 0,4,8,12
            float4 v = make_float4(0.f, 0.f, 0.f, 0.f);
            if (m0 + row < M)
                v = *(const float4*)(A + (size_t)(m0 + row) * K + k0 + kq);
            As[kq + 0][row] = v.x;
            As[kq + 1][row] = v.y;
            As[kq + 2][row] = v.z;
            As[kq + 3][row] = v.w;
        }
        // Load W tile (16 k x 128 n)
        #pragma unroll
        for (int i = 0; i < 2; i++) {
            int idx = tid + i * 256;
            int kk  = idx >> 5;            // 0..15
            int nq  = (idx & 31) << 2;     // 0..124
            *(float4*)(&Ws[kk][nq]) =
                *(const float4*)(W + (size_t)(k0 + kk) * DO + n0 + nq);
        }
        __syncthreads();

        #pragma unroll
        for (int kk = 0; kk < 16; kk++) {
            float ra[8], rb[8];
            *(float4*)(ra)     = *(const float4*)(&As[kk][tm]);
            *(float4*)(ra + 4) = *(const float4*)(&As[kk][tm + 4]);
            *(float4*)(rb)     = *(const float4*)(&Ws[kk][tn]);
            *(float4*)(rb + 4) = *(const float4*)(&Ws[kk][tn + 4]);
            #pragma unroll
            for (int i = 0; i < 8; i++)
                #pragma unroll
                for (int j = 0; j < 8; j++)
                    acc[i][j] += ra[i] * rb[j];
        }
        __syncthreads();
    }

    // Epilogue: bias + relu
    float bv[8];
    #pragma unroll
    for (int j = 0; j < 8; j++) bv[j] = bias[n0 + tn + j];

    #pragma unroll
    for (int i = 0; i < 8; i++) {
        int row = m0 + tm + i;
        if (row < M) {
            float4 o0, o1;
            o0.x = fmaxf(acc[i][0] + bv[0], 0.f);
            o0.y = fmaxf(acc[i][1] + bv[1], 0.f);
            o0.z = fmaxf(acc[i][2] + bv[2], 0.f);
            o0.w = fmaxf(acc[i][3] + bv[3], 0.f);
            o1.x = fmaxf(acc[i][4] + bv[4], 0.f);
            o1.y = fmaxf(acc[i][5] + bv[5], 0.f);
            o1.z = fmaxf(acc[i][6] + bv[6], 0.f);
            o1.w = fmaxf(acc[i][7] + bv[7], 0.f);
            float* cp = C + (size_t)row * DO + n0 + tn;
            *(float4*)(cp)     = o0;
            *(float4*)(cp + 4) = o1;
        }
    }
}

// ---------------------------------------------------------------------------
// Copy epsilon passthrough (second tuple output)
// ---------------------------------------------------------------------------
__global__ void k_copy_eps(const float* __restrict__ eps, float* __restrict__ out) {
    size_t i = (size_t)blockIdx.x * blockDim.x + threadIdx.x;
    const size_t total4 = (size_t)SSN * NN * DNZ / 4;   // 1,600,000 float4
    if (i < total4)
        ((float4*)out)[i] = ((const float4*)eps)[i];
}

// ---------------------------------------------------------------------------
// Entry point (graph-capturable: kernel launches only)
// ---------------------------------------------------------------------------
extern "C" void kernel_launch(void* const* d_in, const int* in_sizes, int n_in,
                              void* d_out, int out_size) {
    const float* X    = (const float*)d_in[0];
    const float* eps  = (const float*)d_in[1];
    const int*   esrc = (const int*)d_in[2];
    const int*   edst = (const int*)d_in[3];
    const float* W0   = (const float*)d_in[4];
    const float* b0   = (const float*)d_in[5];
    const float* W1   = (const float*)d_in[6];
    const float* b1   = (const float*)d_in[7];
    const float* e0   = (const float*)d_in[8];
    const float* e1   = (const float*)d_in[9];
    float* out = (float*)d_out;

    void *pz0 = nullptr, *ph1 = nullptr, *pz1 = nullptr;
    cudaGetSymbolAddress(&pz0, g_z0);
    cudaGetSymbolAddress(&ph1, g_h1);
    cudaGetSymbolAddress(&pz1, g_z1);

    // 1) CSR build
    k_zero_cursor<<<(NN + 255) / 256, 256>>>();
    k_count<<<(NE + 255) / 256, 256>>>(edst);
    k_scan<<<1, 1024>>>();
    k_fill<<<(NE + 255) / 256, 256>>>(esrc, edst);

    // 2) Layer 0: aggregate + GEMM(192->256) + relu
    k_agg0<<<NN, 256>>>(X, eps, e0);
    dim3 gg((MTOT + 127) / 128, DO / 128);
    k_gemm<DH0><<<gg, 256>>>((const float*)pz0, W0, b0, (float*)ph1);

    // 3) Layer 1: aggregate + GEMM(256->256) + relu (outer relu is idempotent)
    k_agg1<<<NN, 256>>>(e1);
    k_gemm<DO><<<gg, 256>>>((const float*)pz1, W1, b1, out);

    // 4) epsilon passthrough as second output (if the harness expects it)
    const long long out_elems = (long long)SSN * NN * DO;           // 25,600,000
    const long long eps_elems = (long long)SSN * NN * DNZ;          //  6,400,000
    if ((long long)out_size >= out_elems + eps_elems) {
        int blocks = (int)((eps_elems / 4 + 255) / 256);
        k_copy_eps<<<blocks, 256>>>(eps, out + out_elems);
    }
}